// round 9
// baseline (speedup 1.0000x reference)
#include <cuda_runtime.h>
#include <cuda_bf16.h>
#include <cstdint>

#define N_NODES 2048
#define NQ (N_NODES / 4)          // 512 float4 per row
#define EPS 0.01f
#define THREADS 256
#define CHUNKS 74                 // per batch -> 8*74 = 592 CTAs = 148 SMs * 4
#define PF 2                      // lookahead distance (rows)

__device__ unsigned long long g_combined = 0ULL;  // [arrivals:32 | count:32]

__device__ __forceinline__ int pair4(const float4 w, const float pi, const float4 pj)
{
    int c = 0;
    c += (w.x == 1.0f) & (fabsf(pi - pj.x) < EPS);
    c += (w.y == 1.0f) & (fabsf(pi - pj.y) < EPS);
    c += (w.z == 1.0f) & (fabsf(pi - pj.z) < EPS);
    c += (w.w == 1.0f) & (fabsf(pi - pj.w) < EPS);
    return c;
}

__global__ void __launch_bounds__(THREADS, 4) count_kernel(
    const float* __restrict__ W, const float* __restrict__ pred,
    float* __restrict__ out, int nblocks)
{
    const int bid = blockIdx.x;
    const int b   = bid / CHUNKS;
    const int c   = bid % CHUNKS;
    const int start = (c * N_NODES) / CHUNKS;
    const int end   = ((c + 1) * N_NODES) / CHUNKS;   // 27 or 28 rows, same batch
    const int tid = threadIdx.x;

    const float* predb = pred + ((size_t)b << 11);
    const float4* Wt = (const float4*)(W + (size_t)(2 * b + 1) * (size_t)N_NODES * N_NODES)
                       + (size_t)start * NQ + tid;

    // 4-slot register ring, 2-row lookahead
    float4 w0[4], w1[4];
    float  pi[4];

    // --- prologue: start the W stream FIRST (DRAM busy from cycle ~0) ---
    #pragma unroll
    for (int k = 0; k < PF; ++k) {
        if (start + k < end) {
            const float4* wn = Wt + (size_t)k * NQ;
            w0[k] = __ldcs(wn);
            w1[k] = __ldcs(wn + THREADS);
        }
    }

    // per-thread fixed column groups (L2-hot after first CTA of each batch)
    const float4 pj0 = __ldg((const float4*)predb + tid);
    const float4 pj1 = __ldg((const float4*)predb + tid + THREADS);
    #pragma unroll
    for (int k = 0; k < PF; ++k)
        if (start + k < end)
            pi[k] = __ldg(predb + start + k);

    int cnt = 0;
    #pragma unroll 4
    for (int r = start; r < end; ++r) {
        const int i = (r - start) & 3;
        if (r + PF < end) {
            const int j = (r + PF - start) & 3;
            const float4* wn = Wt + (size_t)(r + PF - start) * NQ;
            w0[j] = __ldcs(wn);
            w1[j] = __ldcs(wn + THREADS);
            pi[j] = __ldg(predb + r + PF);
        }
        cnt += pair4(w0[i], pi[i], pj0);
        cnt += pair4(w1[i], pi[i], pj1);
    }

    // block reduce
    #pragma unroll
    for (int o = 16; o > 0; o >>= 1)
        cnt += __shfl_xor_sync(0xffffffffu, cnt, o);

    __shared__ int warpsum[THREADS / 32];
    if ((tid & 31) == 0)
        warpsum[tid >> 5] = cnt;
    __syncthreads();

    if (tid == 0) {
        int v = 0;
        #pragma unroll
        for (int i = 0; i < THREADS / 32; ++i)
            v += warpsum[i];
        // one packed RMW: arrivals in high 32, count in low 32. RMW total order
        // guarantees the last arriver's return value holds the full sum.
        unsigned long long old =
            atomicAdd(&g_combined, (1ULL << 32) | (unsigned long long)(unsigned)v);
        if ((unsigned)(old >> 32) == (unsigned)(nblocks - 1)) {
            const unsigned total = (unsigned)old + (unsigned)v;
            out[0] = (float)total;
            g_combined = 0ULL;   // reset for next graph replay (deterministic)
        }
    }
}

extern "C" void kernel_launch(void* const* d_in, const int* in_sizes, int n_in,
                              void* d_out, int out_size)
{
    const float* W    = (const float*)d_in[0];
    const float* pred = (const float*)d_in[1];
    float* out = (float*)d_out;

    const int B = in_sizes[1] / N_NODES;
    const int nblocks = B * CHUNKS;     // 592
    count_kernel<<<nblocks, THREADS>>>(W, pred, out, nblocks);
}

// round 10
// speedup vs baseline: 1.3347x; 1.3347x over previous
#include <cuda_runtime.h>
#include <cuda_bf16.h>
#include <cstdint>

#define N_NODES 2048
#define NQ (N_NODES / 4)          // 512 float4 per row
#define EPS 0.01f
#define THREADS 256
#define CHUNKS 74                 // per batch -> 8*74 = 592 CTAs = 148 SMs * 4

__device__ unsigned long long g_combined = 0ULL;  // [arrivals:32 | count:32]

__device__ __forceinline__ int pair4(const float4 w, const float pi, const float4 pj)
{
    int c = 0;
    c += (w.x == 1.0f) & (fabsf(pi - pj.x) < EPS);
    c += (w.y == 1.0f) & (fabsf(pi - pj.y) < EPS);
    c += (w.z == 1.0f) & (fabsf(pi - pj.z) < EPS);
    c += (w.w == 1.0f) & (fabsf(pi - pj.w) < EPS);
    return c;
}

__device__ __forceinline__ float4 sel3(int phase, float4 a, float4 b, float4 c)
{
    float4 r;
    r.x = (phase == 0) ? a.x : (phase == 1) ? b.x : c.x;
    r.y = (phase == 0) ? a.y : (phase == 1) ? b.y : c.y;
    r.z = (phase == 0) ? a.z : (phase == 1) ? b.z : c.z;
    r.w = (phase == 0) ? a.w : (phase == 1) ? b.w : c.w;
    return r;
}

__global__ void __launch_bounds__(THREADS, 4) count_kernel(
    const float* __restrict__ W, const float* __restrict__ pred,
    float* __restrict__ out, int nblocks)
{
    const int bid = blockIdx.x;
    const int b   = bid / CHUNKS;
    const int c   = bid % CHUNKS;
    const int start = (c * N_NODES) / CHUNKS;
    const int end   = ((c + 1) * N_NODES) / CHUNKS;   // n = 27 or 28 rows (>= 3)
    const int n = end - start;
    const int tid = threadIdx.x;

    const float* predb = pred + ((size_t)b << 11);
    const float4* Wt = (const float4*)(W + (size_t)(2 * b + 1) * (size_t)N_NODES * N_NODES)
                       + (size_t)start * NQ + tid;

    // 3-slot register ring, 2-row lookahead. n>=27 so prologue is unconditional.
    float4 w0a, w1a, w0b, w1b, w0c, w1c;
    float  pia, pib, pic;

    // --- prologue: W stream first (DRAM busy from cycle ~0), rows 0 and 1 ---
    w0a = __ldcs(Wt);
    w1a = __ldcs(Wt + THREADS);
    w0b = __ldcs(Wt + NQ);
    w1b = __ldcs(Wt + NQ + THREADS);

    const float4 pj0 = __ldg((const float4*)predb + tid);
    const float4 pj1 = __ldg((const float4*)predb + tid + THREADS);
    pia = __ldg(predb + start);
    pib = __ldg(predb + start + 1);

    int cnt = 0;
    // steady state: consume row r, load row r+2. No conditionals inside.
    #pragma unroll 3
    for (int r = 0; r < n - 2; ++r) {
        const float4* wn = Wt + (size_t)(r + 2) * NQ;
        const int ph = r % 3;
        if (ph == 0) {
            w0c = __ldcs(wn); w1c = __ldcs(wn + THREADS);
            pic = __ldg(predb + start + r + 2);
            cnt += pair4(w0a, pia, pj0);
            cnt += pair4(w1a, pia, pj1);
        } else if (ph == 1) {
            w0a = __ldcs(wn); w1a = __ldcs(wn + THREADS);
            pia = __ldg(predb + start + r + 2);
            cnt += pair4(w0b, pib, pj0);
            cnt += pair4(w1b, pib, pj1);
        } else {
            w0b = __ldcs(wn); w1b = __ldcs(wn + THREADS);
            pib = __ldg(predb + start + r + 2);
            cnt += pair4(w0c, pic, pj0);
            cnt += pair4(w1c, pic, pj1);
        }
    }
    // epilogue: consume the last two rows (phases (n-2)%3 and (n-1)%3)
    {
        const int p0 = (n - 2) % 3;
        float4 a = sel3(p0, w0a, w0b, w0c);
        float4 bq = sel3(p0, w1a, w1b, w1c);
        float  pp = (p0 == 0) ? pia : (p0 == 1) ? pib : pic;
        cnt += pair4(a, pp, pj0);
        cnt += pair4(bq, pp, pj1);

        const int p1 = (n - 1) % 3;
        a  = sel3(p1, w0a, w0b, w0c);
        bq = sel3(p1, w1a, w1b, w1c);
        pp = (p1 == 0) ? pia : (p1 == 1) ? pib : pic;
        cnt += pair4(a, pp, pj0);
        cnt += pair4(bq, pp, pj1);
    }

    // block reduce
    #pragma unroll
    for (int o = 16; o > 0; o >>= 1)
        cnt += __shfl_xor_sync(0xffffffffu, cnt, o);

    __shared__ int warpsum[THREADS / 32];
    if ((tid & 31) == 0)
        warpsum[tid >> 5] = cnt;
    __syncthreads();

    if (tid == 0) {
        int v = 0;
        #pragma unroll
        for (int i = 0; i < THREADS / 32; ++i)
            v += warpsum[i];
        // one packed RMW: arrivals in high 32, count in low 32. RMW total order
        // guarantees the last arriver's return value holds the full sum.
        unsigned long long old =
            atomicAdd(&g_combined, (1ULL << 32) | (unsigned long long)(unsigned)v);
        if ((unsigned)(old >> 32) == (unsigned)(nblocks - 1)) {
            const unsigned total = (unsigned)old + (unsigned)v;
            out[0] = (float)total;
            g_combined = 0ULL;   // reset for next graph replay (deterministic)
        }
    }
}

extern "C" void kernel_launch(void* const* d_in, const int* in_sizes, int n_in,
                              void* d_out, int out_size)
{
    const float* W    = (const float*)d_in[0];
    const float* pred = (const float*)d_in[1];
    float* out = (float*)d_out;

    const int B = in_sizes[1] / N_NODES;
    const int nblocks = B * CHUNKS;     // 592
    count_kernel<<<nblocks, THREADS>>>(W, pred, out, nblocks);
}

// round 11
// speedup vs baseline: 1.6465x; 1.2336x over previous
#include <cuda_runtime.h>
#include <cuda_bf16.h>
#include <cstdint>

#define N_NODES 2048
#define NQ (N_NODES / 4)          // 512 float4 per row
#define EPS 0.01f
#define THREADS 256
#define CTAS_PER_SM 6
#define CHUNKS 111                // per batch -> 8*111 = 888 CTAs = 148 SMs * 6

__device__ unsigned long long g_combined = 0ULL;  // [arrivals:32 | count:32]

__device__ __forceinline__ int pair4(const float4 w, const float pi, const float4 pj)
{
    int c = 0;
    c += (w.x == 1.0f) & (fabsf(pi - pj.x) < EPS);
    c += (w.y == 1.0f) & (fabsf(pi - pj.y) < EPS);
    c += (w.z == 1.0f) & (fabsf(pi - pj.z) < EPS);
    c += (w.w == 1.0f) & (fabsf(pi - pj.w) < EPS);
    return c;
}

__global__ void __launch_bounds__(THREADS, CTAS_PER_SM) count_kernel(
    const float* __restrict__ W, const float* __restrict__ pred,
    float* __restrict__ out, int nblocks)
{
    const int bid = blockIdx.x;
    const int b   = bid / CHUNKS;
    const int c   = bid % CHUNKS;
    const int start = (c * N_NODES) / CHUNKS;
    const int end   = ((c + 1) * N_NODES) / CHUNKS;   // 18 or 19 rows, same batch
    const int tid = threadIdx.x;

    const float* predb = pred + ((size_t)b << 11);
    const float4* Wt = (const float4*)(W + (size_t)(2 * b + 1) * (size_t)N_NODES * N_NODES)
                       + (size_t)start * NQ + tid;

    // --- prologue: start the W stream FIRST (DRAM busy from cycle ~0) ---
    float4 w0[2], w1[2];
    float  pi[2];
    w0[0] = __ldcs(Wt);
    w1[0] = __ldcs(Wt + THREADS);

    // per-thread fixed column groups (L2-hot after first CTA of each batch)
    const float4 pj0 = __ldg((const float4*)predb + tid);
    const float4 pj1 = __ldg((const float4*)predb + tid + THREADS);
    pi[0] = __ldg(predb + start);

    int cnt = 0;
    int p = 0;
    #pragma unroll 2
    for (int r = start; r < end; ++r) {
        const int nxt = p ^ 1;
        if (r + 1 < end) {
            const float4* wn = Wt + (size_t)(r + 1 - start) * NQ;
            w0[nxt] = __ldcs(wn);
            w1[nxt] = __ldcs(wn + THREADS);
            pi[nxt] = __ldg(predb + r + 1);
        }
        cnt += pair4(w0[p], pi[p], pj0);
        cnt += pair4(w1[p], pi[p], pj1);
        p = nxt;
    }

    // block reduce
    #pragma unroll
    for (int o = 16; o > 0; o >>= 1)
        cnt += __shfl_xor_sync(0xffffffffu, cnt, o);

    __shared__ int warpsum[THREADS / 32];
    if ((tid & 31) == 0)
        warpsum[tid >> 5] = cnt;
    __syncthreads();

    if (tid == 0) {
        int v = 0;
        #pragma unroll
        for (int i = 0; i < THREADS / 32; ++i)
            v += warpsum[i];
        // one packed RMW: arrivals in high 32, count in low 32. RMW total order
        // guarantees the last arriver's return value holds the full sum.
        unsigned long long old =
            atomicAdd(&g_combined, (1ULL << 32) | (unsigned long long)(unsigned)v);
        if ((unsigned)(old >> 32) == (unsigned)(nblocks - 1)) {
            const unsigned total = (unsigned)old + (unsigned)v;
            out[0] = (float)total;
            g_combined = 0ULL;   // reset for next graph replay (deterministic)
        }
    }
}

extern "C" void kernel_launch(void* const* d_in, const int* in_sizes, int n_in,
                              void* d_out, int out_size)
{
    const float* W    = (const float*)d_in[0];
    const float* pred = (const float*)d_in[1];
    float* out = (float*)d_out;

    const int B = in_sizes[1] / N_NODES;
    const int nblocks = B * CHUNKS;     // 888
    count_kernel<<<nblocks, THREADS>>>(W, pred, out, nblocks);
}